// round 7
// baseline (speedup 1.0000x reference)
#include <cuda_runtime.h>

// ---------------- static config ----------------
namespace cfg {
constexpr int NN = 10000;       // nodes
constexpr int NE = 128000;      // edges
constexpr int NWARP = 15;       // warps per conv block
constexpr int CONV_THREADS = NWARP * 32;   // 480
constexpr int EPG = 8;          // edges per warp-group
constexpr int WS = 1800;        // per-warp scratch floats (even -> 8B alignment holds)
// smem floats: W1(48*64) + B1(64) + W2(64*416 permuted) + B2(416) + warp scratch
constexpr int SMEM_FLOATS = 48*64 + 64 + 64*416 + 416 + NWARP*WS;
constexpr int SMEM_BYTES = SMEM_FLOATS * 4;   // 228704
}

typedef unsigned long long ull;

__device__ __forceinline__ ull pk2(float lo, float hi) {
    ull r; asm("mov.b64 %0, {%1,%2};" : "=l"(r) : "f"(lo), "f"(hi)); return r;
}
__device__ __forceinline__ float2 upk2(ull v) {
    float2 f; asm("mov.b64 {%0,%1}, %2;" : "=f"(f.x), "=f"(f.y) : "l"(v)); return f;
}
__device__ __forceinline__ ull ffma2(ull a, ull b, ull c) {
    ull d; asm("fma.rn.f32x2 %0, %1, %2, %3;" : "=l"(d) : "l"(a), "l"(b), "l"(c)); return d;
}

// ---------------- device scratch (no allocations allowed) ----------------
__device__ float g_h0[cfg::NN * 16];
__device__ float g_h1[cfg::NN * 12];
__device__ float g_acc0[cfg::NN * 16];
__device__ float g_acc1[cfg::NN * 12];
__device__ float g_cnt[cfg::NN];
__device__ float g_eattr[cfg::NE * 16];
__device__ float g_y1[cfg::NE * 3];

// ---------------- zero scratch ----------------
__global__ void zero_kernel() {
    int i = blockIdx.x * blockDim.x + threadIdx.x;
    int stride = gridDim.x * blockDim.x;
    for (int t = i; t < cfg::NN * 16; t += stride) g_acc0[t] = 0.f;
    for (int t = i; t < cfg::NN * 12; t += stride) { g_acc1[t] = 0.f; g_h1[t] = 0.f; }
    for (int t = i; t < cfg::NN; t += stride) g_cnt[t] = 0.f;
}

// ---------------- node encoder + node_embedding MLP ----------------
__global__ void node_init_kernel(const float* __restrict__ nf,
                                 const float* __restrict__ encW, const float* __restrict__ encB,
                                 const float* __restrict__ W1, const float* __restrict__ B1,
                                 const float* __restrict__ W2, const float* __restrict__ B2) {
    int n = blockIdx.x * blockDim.x + threadIdx.x;
    if (n >= cfg::NN) return;
    float enc[16];
    #pragma unroll
    for (int c = 0; c < 16; c++) enc[c] = encB[c];
    for (int f = 0; f < 64; f++) {
        float v = nf[n * 64 + f];
        #pragma unroll
        for (int c = 0; c < 16; c++) enc[c] = fmaf(v, encW[f * 16 + c], enc[c]);
    }
    float t[16];
    #pragma unroll
    for (int c = 0; c < 16; c++) {
        float a = B1[c];
        #pragma unroll
        for (int j = 0; j < 16; j++) a = fmaf(enc[j], W1[j * 16 + c], a);
        t[c] = fmaxf(a, 0.f);
    }
    #pragma unroll
    for (int c = 0; c < 16; c++) {
        float a = B2[c];
        #pragma unroll
        for (int j = 0; j < 16; j++) a = fmaf(t[j], W2[j * 16 + c], a);
        g_h0[n * 16 + c] = a;
    }
}

// ---------------- per-edge: geometry, rbf, edge_attr, degree count ----------------
__global__ void edge_init_kernel(const float* __restrict__ pos,
                                 const float* __restrict__ eain, const int* __restrict__ ei,
                                 const float* __restrict__ eeW1, const float* __restrict__ eeB1,
                                 const float* __restrict__ eeW2, const float* __restrict__ eeB2,
                                 const float* __restrict__ reW1, const float* __restrict__ reB1,
                                 const float* __restrict__ reW2, const float* __restrict__ reB2) {
    int e = blockIdx.x * blockDim.x + threadIdx.x;
    if (e >= cfg::NE) return;
    int sn = ei[e], dn = ei[cfg::NE + e];
    float vx = pos[sn * 3 + 0] - pos[dn * 3 + 0];
    float vy = pos[sn * 3 + 1] - pos[dn * 3 + 1];
    float vz = pos[sn * 3 + 2] - pos[dn * 3 + 2];
    float d = sqrtf(vx * vx + vy * vy + vz * vz);
    float dmx = fmaxf(d, 1e-9f);
    float s = 1.7320508075688772f / dmx;     // sqrt(3) * unit
    g_y1[e * 3 + 0] = s * vx;
    g_y1[e * 3 + 1] = s * vy;
    g_y1[e * 3 + 2] = s * vz;
    atomicAdd(&g_cnt[sn], 1.f);

    float xin[16];
    #pragma unroll
    for (int j = 0; j < 16; j++) xin[j] = eain[e * 16 + j];
    float he[16];
    #pragma unroll
    for (int c = 0; c < 16; c++) {
        float a = eeB1[c];
        #pragma unroll
        for (int j = 0; j < 16; j++) a = fmaf(xin[j], eeW1[j * 16 + c], a);
        he[c] = fmaxf(a, 0.f);
    }
    const float step = 12.0f / 31.0f;
    const float coeff = -0.5f / (step * step);
    float hr[16];
    #pragma unroll
    for (int c = 0; c < 16; c++) hr[c] = reB1[c];
    #pragma unroll 4
    for (int r = 0; r < 32; r++) {
        float t = d - (float)r * step;
        float rb = __expf(coeff * t * t);
        #pragma unroll
        for (int c = 0; c < 16; c++) hr[c] = fmaf(rb, reW1[r * 16 + c], hr[c]);
    }
    #pragma unroll
    for (int c = 0; c < 16; c++) hr[c] = fmaxf(hr[c], 0.f);
    #pragma unroll
    for (int c = 0; c < 16; c++) {
        float a = eeB2[c] + reB2[c];
        #pragma unroll
        for (int j = 0; j < 16; j++)
            a = fmaf(he[j], eeW2[j * 16 + c], fmaf(hr[j], reW2[j * 16 + c], a));
        g_eattr[e * 16 + c] = a;
    }
}

// ---------------- conv layer: per-edge weight MLP + tensor product + scatter ----------------
// fc2 weight smem layout (per k row of 416):
//   [0,384): 6 column-pairs interleaved: dest = j*64 + lane*2 + s  <=  src col i=2j+s, lane
//   [384,416): scalar block i=12 at original position
// fc2 done in TWO sequential passes within one warp (j=0..2, then j=3..5 + scalar)
// to halve accumulator registers -> 15 warps/SM at <=136 regs.
__global__ void __launch_bounds__(cfg::CONV_THREADS, 1)
conv_kernel(const int* __restrict__ ei,
            const float* __restrict__ W1g, const float* __restrict__ B1g,
            const float* __restrict__ W2g, const float* __restrict__ B2g) {
    extern __shared__ float smem[];
    float* sW1 = smem;               // [48][64]
    float* sB1 = sW1 + 3072;         // [64]
    float* sW2 = sB1 + 64;           // [64][416] permuted
    float* sB2 = sW2 + 26624;        // [416]
    float* sWS = sB2 + 416;

    for (int t = threadIdx.x; t < 3072; t += blockDim.x) sW1[t] = W1g[t];
    for (int t = threadIdx.x; t < 64; t += blockDim.x) sB1[t] = B1g[t];
    for (int t = threadIdx.x; t < 26624; t += blockDim.x) {
        int k = t / 416, p = t - k * 416;
        int dest;
        if (p < 384) {
            int i = p >> 5, l = p & 31;
            dest = k * 416 + (i >> 1) * 64 + l * 2 + (i & 1);
        } else {
            dest = t;
        }
        sW2[dest] = W2g[t];
    }
    for (int t = threadIdx.x; t < 416; t += blockDim.x) sB2[t] = B2g[t];
    __syncthreads();

    const int lane = threadIdx.x & 31;
    const int warp = threadIdx.x >> 5;
    float* ws    = sWS + warp * cfg::WS;
    float* s_ea  = ws;          // [48][8] interleaved: s_ea[c*8+e]
    float* s_h   = ws + 384;    // [64][18] dup pairs: s_h[k*18+2e{,+1}] = h[k][e]
    float* s_x1  = ws + 1536;   // [8][4][3]
    float* s_y1  = ws + 1632;   // [8][3]
    float* s_dot = ws + 1656;   // [8][4]
    float* s_cr  = ws + 1688;   // [8][4][3]
    int*   s_idx = (int*)(ws + 1784); // [16]: src 0..7, dst 8..15

    const unsigned FULL = 0xffffffffu;
    const int numGroups = cfg::NE / cfg::EPG;   // 16000
    const int warpsTotal = gridDim.x * cfg::NWARP;

    for (int g = blockIdx.x * cfg::NWARP + warp; g < numGroups; g += warpsTotal) {
        const int ebase = g * cfg::EPG;

        // ---- phase 1: gather edge features (8 edges), interleaved layout ----
        if (lane < 8) s_idx[lane] = ei[ebase + lane];
        else if (lane < 16) s_idx[lane] = ei[cfg::NE + ebase + (lane - 8)];
        __syncwarp();
        #pragma unroll
        for (int j = 0; j < 12; j++) {
            int t = lane + 32 * j;          // 0..383
            int e = t / 48;
            int c = t - e * 48;
            float v;
            if (c < 16) {
                v = g_eattr[(ebase + e) * 16 + c];
            } else if (c < 32) {
                v = g_h0[s_idx[e] * 16 + (c - 16)];
            } else {
                v = g_h0[s_idx[8 + e] * 16 + (c - 32)];
            }
            s_ea[c * 8 + e] = v;
        }
        if (lane < 24) {
            int e = lane / 3, m = lane - e * 3;
            s_y1[lane] = g_y1[(ebase + e) * 3 + m];
        }
        {
            int e = lane >> 2, n = lane & 3;
            int dn = s_idx[8 + e];
            s_x1[e * 12 + n * 3 + 0] = g_h1[dn * 12 + n * 3 + 0];
            s_x1[e * 12 + n * 3 + 1] = g_h1[dn * 12 + n * 3 + 1];
            s_x1[e * 12 + n * 3 + 2] = g_h1[dn * 12 + n * 3 + 2];
        }
        __syncwarp();
        {
            int e = lane >> 2, n = lane & 3;
            float xa = s_x1[e * 12 + n * 3 + 0], xb = s_x1[e * 12 + n * 3 + 1], xc = s_x1[e * 12 + n * 3 + 2];
            float ya = s_y1[e * 3 + 0], yb = s_y1[e * 3 + 1], yc = s_y1[e * 3 + 2];
            s_dot[e * 4 + n] = (xa * ya + xb * yb + xc * yc) * 0.57735026918962576f;
            s_cr[e * 12 + n * 3 + 0] = (xb * yc - xc * yb) * 0.70710678118654752f;
            s_cr[e * 12 + n * 3 + 1] = (xc * ya - xa * yc) * 0.70710678118654752f;
            s_cr[e * 12 + n * 3 + 2] = (xa * yb - xb * ya) * 0.70710678118654752f;
        }
        __syncwarp();

        // ---- phase 2: fc1 (48 -> 64, relu), FFMA2 over edge pairs ----
        // lane owns hidden k = lane and lane+32; stores DUPLICATED (h,h) pairs.
        {
            ull hacc[2][4];
            #pragma unroll
            for (int kk = 0; kk < 2; kk++) {
                float b = sB1[lane + 32 * kk];
                ull bb = pk2(b, b);
                #pragma unroll
                for (int p = 0; p < 4; p++) hacc[kk][p] = bb;
            }
            #pragma unroll 4
            for (int c = 0; c < 48; c++) {
                ull vp[4];
                #pragma unroll
                for (int p = 0; p < 4; p++)
                    vp[p] = *(const ull*)(s_ea + c * 8 + 2 * p);
                float w1a = sW1[c * 64 + lane];
                float w1b = sW1[c * 64 + lane + 32];
                ull wa2 = pk2(w1a, w1a), wb2 = pk2(w1b, w1b);
                #pragma unroll
                for (int p = 0; p < 4; p++) {
                    hacc[0][p] = ffma2(vp[p], wa2, hacc[0][p]);
                    hacc[1][p] = ffma2(vp[p], wb2, hacc[1][p]);
                }
            }
            #pragma unroll
            for (int kk = 0; kk < 2; kk++) {
                float* hrow = s_h + (lane + 32 * kk) * 18;
                #pragma unroll
                for (int p = 0; p < 4; p++) {
                    float2 f = upk2(hacc[kk][p]);
                    f.x = fmaxf(f.x, 0.f); f.y = fmaxf(f.y, 0.f);
                    *(ull*)(hrow + 4 * p)     = pk2(f.x, f.x);
                    *(ull*)(hrow + 4 * p + 2) = pk2(f.y, f.y);
                }
            }
        }
        __syncwarp();

        // ================= fc2 PASS A: pairs j=0..2 (i=0..5), then phase4-A =================
        {
            ull acc[cfg::EPG][3];
            #pragma unroll
            for (int jl = 0; jl < 3; jl++) {
                ull b2 = pk2(sB2[lane + 64 * jl], sB2[lane + 64 * jl + 32]);
                #pragma unroll
                for (int e = 0; e < cfg::EPG; e++) acc[e][jl] = b2;
            }
            #pragma unroll 2
            for (int k = 0; k < 64; k++) {
                const float* rw = sW2 + k * 416;
                ull w2p[3];
                #pragma unroll
                for (int jl = 0; jl < 3; jl++)
                    w2p[jl] = *(const ull*)(rw + jl * 64 + lane * 2);
                const float* hk = s_h + k * 18;
                #pragma unroll
                for (int e = 0; e < cfg::EPG; e++) {
                    ull hh = *(const ull*)(hk + 2 * e);     // (h,h) duplicated
                    #pragma unroll
                    for (int jl = 0; jl < 3; jl++)
                        acc[e][jl] = ffma2(hh, w2p[jl], acc[e][jl]);
                }
            }
            // phase4-A: w00 i=0..5 -> partial ro0
            #pragma unroll
            for (int e = 0; e < cfg::EPG; e++) {
                float w[6];
                #pragma unroll
                for (int jl = 0; jl < 3; jl++) {
                    float2 f = upk2(acc[e][jl]);
                    w[2 * jl] = f.x; w[2 * jl + 1] = f.y;
                }
                const float* x0p = s_ea + 32 * 8 + e;   // h0[dst], stride 8
                float ro0 = 0.f;
                #pragma unroll
                for (int i = 0; i < 6; i++) {
                    int n = 2 * i + (lane >> 4);
                    float c = w[i] * x0p[n * 8];
                    ro0 += c + __shfl_xor_sync(FULL, c, 16);
                }
                int sn = s_idx[e];
                if (lane < 16)
                    atomicAdd(&g_acc0[sn * 16 + lane], 0.22360679774997896f * ro0);
            }
        }

        // ================= fc2 PASS B: pairs j=3..5 + scalar (i=6..12), then phase4-B =================
        {
            ull acc[cfg::EPG][3];
            float accs[cfg::EPG];
            #pragma unroll
            for (int jl = 0; jl < 3; jl++) {
                ull b2 = pk2(sB2[lane + 64 * (3 + jl)], sB2[lane + 64 * (3 + jl) + 32]);
                #pragma unroll
                for (int e = 0; e < cfg::EPG; e++) acc[e][jl] = b2;
            }
            {
                float bs = sB2[384 + lane];
                #pragma unroll
                for (int e = 0; e < cfg::EPG; e++) accs[e] = bs;
            }
            #pragma unroll 2
            for (int k = 0; k < 64; k++) {
                const float* rw = sW2 + k * 416;
                ull w2p[3];
                #pragma unroll
                for (int jl = 0; jl < 3; jl++)
                    w2p[jl] = *(const ull*)(rw + (3 + jl) * 64 + lane * 2);
                float w2s = rw[384 + lane];
                const float* hk = s_h + k * 18;
                #pragma unroll
                for (int e = 0; e < cfg::EPG; e++) {
                    ull hh = *(const ull*)(hk + 2 * e);
                    float h = upk2(hh).x;                   // free: low half of reg pair
                    #pragma unroll
                    for (int jl = 0; jl < 3; jl++)
                        acc[e][jl] = ffma2(hh, w2p[jl], acc[e][jl]);
                    accs[e] = fmaf(h, w2s, accs[e]);
                }
            }
            // phase4-B: i = 6..12 -> rest of w00, w011, w101, w110, w111
            #pragma unroll
            for (int e = 0; e < cfg::EPG; e++) {
                float w[7];
                #pragma unroll
                for (int jl = 0; jl < 3; jl++) {
                    float2 f = upk2(acc[e][jl]);
                    w[2 * jl] = f.x; w[2 * jl + 1] = f.y;   // i = 6+2jl, 7+2jl
                }
                w[6] = accs[e];                              // i = 12

                const float* x0p = s_ea + 32 * 8 + e;
                float ro0 = 0.f, rt = 0.f, r1a = 0.f, r1b = 0.f, r1c = 0.f;
                // i=6,7: w00 tail
                #pragma unroll
                for (int i = 6; i < 8; i++) {
                    int n = 2 * i + (lane >> 4);
                    float c = w[i - 6] * x0p[n * 8];
                    ro0 += c + __shfl_xor_sync(FULL, c, 16);
                }
                // i=8,9: w011 -> t011[o=lane&3]
                #pragma unroll
                for (int i = 8; i < 10; i++) {
                    int n = ((i - 8) * 32 + lane) >> 2;
                    float c = w[i - 6] * x0p[n * 8];
                    c += __shfl_xor_sync(FULL, c, 4);
                    c += __shfl_xor_sync(FULL, c, 8);
                    c += __shfl_xor_sync(FULL, c, 16);
                    rt += c;
                }
                {   // i=10: low lanes w101 (n=lane/4,o=lane&3), high lanes w110 (n=0)
                    float wv = w[4];
                    float c = (lane >= 16) ? wv * s_dot[e * 4 + 0] : 0.f;
                    ro0 += c + __shfl_xor_sync(FULL, c, 16);
                    int n = (lane & 15) >> 2;
                    const float* xp = s_x1 + e * 12 + n * 3;
                    float m0 = (lane < 16) ? wv * xp[0] : 0.f;
                    float m1 = (lane < 16) ? wv * xp[1] : 0.f;
                    float m2 = (lane < 16) ? wv * xp[2] : 0.f;
                    m0 += __shfl_xor_sync(FULL, m0, 4); m0 += __shfl_xor_sync(FULL, m0, 8);
                    m1 += __shfl_xor_sync(FULL, m1, 4); m1 += __shfl_xor_sync(FULL, m1, 8);
                    m2 += __shfl_xor_sync(FULL, m2, 4); m2 += __shfl_xor_sync(FULL, m2, 8);
                    r1a += m0; r1b += m1; r1c += m2;
                }
                {   // i=11: all w110, n = 1 (low) / 2 (high)
                    float c = w[5] * s_dot[e * 4 + ((lane < 16) ? 1 : 2)];
                    ro0 += c + __shfl_xor_sync(FULL, c, 16);
                }
                {   // i=12: low lanes w110 (n=3), high lanes w111
                    float wv = w[6];
                    float c = (lane < 16) ? wv * s_dot[e * 4 + 3] : 0.f;
                    ro0 += c + __shfl_xor_sync(FULL, c, 16);
                    int n = (lane & 15) >> 2;
                    const float* cp = s_cr + e * 12 + n * 3;
                    float m0 = (lane >= 16) ? wv * cp[0] : 0.f;
                    float m1 = (lane >= 16) ? wv * cp[1] : 0.f;
                    float m2 = (lane >= 16) ? wv * cp[2] : 0.f;
                    m0 += __shfl_xor_sync(FULL, m0, 4); m0 += __shfl_xor_sync(FULL, m0, 8); m0 += __shfl_xor_sync(FULL, m0, 16);
                    m1 += __shfl_xor_sync(FULL, m1, 4); m1 += __shfl_xor_sync(FULL, m1, 8); m1 += __shfl_xor_sync(FULL, m1, 16);
                    m2 += __shfl_xor_sync(FULL, m2, 4); m2 += __shfl_xor_sync(FULL, m2, 8); m2 += __shfl_xor_sync(FULL, m2, 16);
                    r1a += m0; r1b += m1; r1c += m2;
                }
                r1a += rt * s_y1[e * 3 + 0];
                r1b += rt * s_y1[e * 3 + 1];
                r1c += rt * s_y1[e * 3 + 2];

                int sn = s_idx[e];
                if (lane < 16)
                    atomicAdd(&g_acc0[sn * 16 + lane], 0.22360679774997896f * ro0);
                if (lane < 4) {
                    atomicAdd(&g_acc1[sn * 12 + lane * 3 + 0], 0.20412414523193150f * r1a);
                    atomicAdd(&g_acc1[sn * 12 + lane * 3 + 1], 0.20412414523193150f * r1b);
                    atomicAdd(&g_acc1[sn * 12 + lane * 3 + 2], 0.20412414523193150f * r1c);
                }
            }
        }
        __syncwarp();
    }
}

// ---------------- scatter-mean residual update, zero accumulators ----------------
__global__ void update_kernel() {
    int i = blockIdx.x * blockDim.x + threadIdx.x;
    if (i < cfg::NN * 16) {
        int n = i >> 4;
        float inv = 1.f / fmaxf(g_cnt[n], 1.f);
        g_h0[i] += g_acc0[i] * inv;
        g_acc0[i] = 0.f;
    }
    if (i < cfg::NN * 12) {
        int n = i / 12;
        float inv = 1.f / fmaxf(g_cnt[n], 1.f);
        g_h1[i] += g_acc1[i] * inv;
        g_acc1[i] = 0.f;
    }
}

// ---------------- final update + o3.Linear + sorter layout ----------------
__global__ void final_kernel(float* __restrict__ out,
                             const float* __restrict__ lin0, const float* __restrict__ lin1) {
    int n = blockIdx.x * blockDim.x + threadIdx.x;
    if (n >= cfg::NN) return;
    float inv = 1.f / fmaxf(g_cnt[n], 1.f);
    float h0f[16];
    #pragma unroll
    for (int s = 0; s < 16; s++) h0f[s] = g_h0[n * 16 + s] + g_acc0[n * 16 + s] * inv;
    float h1f[12];
    #pragma unroll
    for (int s = 0; s < 12; s++) h1f[s] = g_h1[n * 12 + s] + g_acc1[n * 12 + s] * inv;
    float* o = out + (size_t)n * 128;
    #pragma unroll 4
    for (int c = 0; c < 32; c++) {
        float f0 = 0.f;
        #pragma unroll
        for (int s = 0; s < 16; s++) f0 = fmaf(h0f[s], lin0[s * 32 + c], f0);
        o[4 * c] = 0.25f * f0;                 // 1/sqrt(16)
        #pragma unroll
        for (int m = 0; m < 3; m++) {
            float f1 = 0.f;
            #pragma unroll
            for (int v = 0; v < 4; v++) f1 = fmaf(h1f[v * 3 + m], lin1[v * 32 + c], f1);
            o[4 * c + 1 + m] = 0.5f * f1;      // 1/sqrt(4)
        }
    }
}

// ---------------- launch ----------------
extern "C" void kernel_launch(void* const* d_in, const int* in_sizes, int n_in,
                              void* d_out, int out_size) {
    const float* pos          = (const float*)d_in[0];
    const float* node_feats   = (const float*)d_in[1];
    const float* edge_attr_in = (const float*)d_in[2];
    const int*   edge_index   = (const int*)d_in[3];
    const float* enc_W  = (const float*)d_in[4];
    const float* enc_b  = (const float*)d_in[5];
    const float* ne_W1  = (const float*)d_in[6];
    const float* ne_b1  = (const float*)d_in[7];
    const float* ne_W2  = (const float*)d_in[8];
    const float* ne_b2  = (const float*)d_in[9];
    const float* ee_W1  = (const float*)d_in[10];
    const float* ee_b1  = (const float*)d_in[11];
    const float* ee_W2  = (const float*)d_in[12];
    const float* ee_b2  = (const float*)d_in[13];
    const float* re_W1  = (const float*)d_in[14];
    const float* re_b1  = (const float*)d_in[15];
    const float* re_W2  = (const float*)d_in[16];
    const float* re_b2  = (const float*)d_in[17];
    const float* fc1_W  = (const float*)d_in[18];   // [2,48,64]
    const float* fc1_b  = (const float*)d_in[19];   // [2,64]
    const float* fc2_W  = (const float*)d_in[20];   // [2,64,416]
    const float* fc2_b  = (const float*)d_in[21];   // [2,416]
    const float* lin0_W = (const float*)d_in[22];
    const float* lin1_W = (const float*)d_in[23];
    float* out = (float*)d_out;

    int dev = 0;
    cudaGetDevice(&dev);
    int nsm = 148;
    cudaDeviceGetAttribute(&nsm, cudaDevAttrMultiProcessorCount, dev);
    cudaFuncSetAttribute(conv_kernel, cudaFuncAttributeMaxDynamicSharedMemorySize, cfg::SMEM_BYTES);

    zero_kernel<<<256, 256>>>();
    node_init_kernel<<<(cfg::NN + 127) / 128, 128>>>(node_feats, enc_W, enc_b,
                                                     ne_W1, ne_b1, ne_W2, ne_b2);
    edge_init_kernel<<<(cfg::NE + 127) / 128, 128>>>(pos, edge_attr_in, edge_index,
                                                     ee_W1, ee_b1, ee_W2, ee_b2,
                                                     re_W1, re_b1, re_W2, re_b2);
    // layer 0
    conv_kernel<<<nsm, cfg::CONV_THREADS, cfg::SMEM_BYTES>>>(edge_index,
        fc1_W, fc1_b, fc2_W, fc2_b);
    update_kernel<<<(cfg::NN * 16 + 255) / 256, 256>>>();
    // layer 1
    conv_kernel<<<nsm, cfg::CONV_THREADS, cfg::SMEM_BYTES>>>(edge_index,
        fc1_W + 48 * 64, fc1_b + 64, fc2_W + 64 * 416, fc2_b + 416);
    // final update + output projection
    final_kernel<<<(cfg::NN + 127) / 128, 128>>>(out, lin0_W, lin1_W);
}

// round 9
// speedup vs baseline: 2.6606x; 2.6606x over previous
#include <cuda_runtime.h>
#include <cuda_bf16.h>
#include <cstdint>

// ---------------- static config ----------------
namespace cfg {
constexpr int NN = 10000;
constexpr int NE = 128000;
constexpr int NWARP = 16;
constexpr int THREADS = NWARP * 32;     // 512
constexpr int NBLK = NE / 16;           // 8000 16-edge blocks

// smem byte offsets
constexpr int OFF_B2F   = 0;            // fc2 weight frags: [52 nt][4 ks][32 lane] uint4 = 106496B
constexpr int OFF_B1F   = 106496;       // fc1 weight frags: [8 nt][3 ks][32 lane] uint4 = 12288B
constexpr int OFF_BIAS2 = 118784;       // 416 f32
constexpr int OFF_BIAS1 = 120448;       // 64 f32
constexpr int OFF_SLAB  = 120704;       // per-warp slabs: 832 f32 each
constexpr int SLABF     = 832;
constexpr int SMEM_BYTES = OFF_SLAB + NWARP * SLABF * 4;   // 173952
}

// ---------------- helpers ----------------
__device__ __forceinline__ void split2(float x, float y, uint32_t& h, uint32_t& l) {
    __nv_bfloat162 hb = __floats2bfloat162_rn(x, y);        // x -> low, y -> high
    h = *(const uint32_t*)&hb;
    float rx = x - __bfloat162float(hb.x);
    float ry = y - __bfloat162float(hb.y);
    __nv_bfloat162 lb = __floats2bfloat162_rn(rx, ry);
    l = *(const uint32_t*)&lb;
}
__device__ __forceinline__ void mma16816(float (&d)[4], const uint32_t (&a)[4],
                                         uint32_t b0, uint32_t b1) {
    asm volatile(
        "mma.sync.aligned.m16n8k16.row.col.f32.bf16.bf16.f32 "
        "{%0,%1,%2,%3}, {%4,%5,%6,%7}, {%8,%9}, {%0,%1,%2,%3};"
        : "+f"(d[0]), "+f"(d[1]), "+f"(d[2]), "+f"(d[3])
        : "r"(a[0]), "r"(a[1]), "r"(a[2]), "r"(a[3]), "r"(b0), "r"(b1));
}

// ---------------- device scratch ----------------
__device__ float g_h0[cfg::NN * 16];
__device__ float g_h1[cfg::NN * 12];
__device__ float g_acc0[cfg::NN * 16];
__device__ float g_acc1[cfg::NN * 12];
__device__ float g_cnt[cfg::NN];
__device__ float g_eattr[cfg::NE * 16];
__device__ float g_y1[cfg::NE * 3];

// ---------------- zero scratch ----------------
__global__ void zero_kernel() {
    int i = blockIdx.x * blockDim.x + threadIdx.x;
    int stride = gridDim.x * blockDim.x;
    for (int t = i; t < cfg::NN * 16; t += stride) g_acc0[t] = 0.f;
    for (int t = i; t < cfg::NN * 12; t += stride) { g_acc1[t] = 0.f; g_h1[t] = 0.f; }
    for (int t = i; t < cfg::NN; t += stride) g_cnt[t] = 0.f;
}

// ---------------- node encoder + node_embedding MLP ----------------
__global__ void node_init_kernel(const float* __restrict__ nf,
                                 const float* __restrict__ encW, const float* __restrict__ encB,
                                 const float* __restrict__ W1, const float* __restrict__ B1,
                                 const float* __restrict__ W2, const float* __restrict__ B2) {
    int n = blockIdx.x * blockDim.x + threadIdx.x;
    if (n >= cfg::NN) return;
    float enc[16];
    #pragma unroll
    for (int c = 0; c < 16; c++) enc[c] = encB[c];
    for (int f = 0; f < 64; f++) {
        float v = nf[n * 64 + f];
        #pragma unroll
        for (int c = 0; c < 16; c++) enc[c] = fmaf(v, encW[f * 16 + c], enc[c]);
    }
    float t[16];
    #pragma unroll
    for (int c = 0; c < 16; c++) {
        float a = B1[c];
        #pragma unroll
        for (int j = 0; j < 16; j++) a = fmaf(enc[j], W1[j * 16 + c], a);
        t[c] = fmaxf(a, 0.f);
    }
    #pragma unroll
    for (int c = 0; c < 16; c++) {
        float a = B2[c];
        #pragma unroll
        for (int j = 0; j < 16; j++) a = fmaf(t[j], W2[j * 16 + c], a);
        g_h0[n * 16 + c] = a;
    }
}

// ---------------- per-edge init ----------------
__global__ void edge_init_kernel(const float* __restrict__ pos,
                                 const float* __restrict__ eain, const int* __restrict__ ei,
                                 const float* __restrict__ eeW1, const float* __restrict__ eeB1,
                                 const float* __restrict__ eeW2, const float* __restrict__ eeB2,
                                 const float* __restrict__ reW1, const float* __restrict__ reB1,
                                 const float* __restrict__ reW2, const float* __restrict__ reB2) {
    int e = blockIdx.x * blockDim.x + threadIdx.x;
    if (e >= cfg::NE) return;
    int sn = ei[e], dn = ei[cfg::NE + e];
    float vx = pos[sn * 3 + 0] - pos[dn * 3 + 0];
    float vy = pos[sn * 3 + 1] - pos[dn * 3 + 1];
    float vz = pos[sn * 3 + 2] - pos[dn * 3 + 2];
    float d = sqrtf(vx * vx + vy * vy + vz * vz);
    float dmx = fmaxf(d, 1e-9f);
    float s = 1.7320508075688772f / dmx;
    g_y1[e * 3 + 0] = s * vx;
    g_y1[e * 3 + 1] = s * vy;
    g_y1[e * 3 + 2] = s * vz;
    atomicAdd(&g_cnt[sn], 1.f);

    float xin[16];
    #pragma unroll
    for (int j = 0; j < 16; j++) xin[j] = eain[e * 16 + j];
    float he[16];
    #pragma unroll
    for (int c = 0; c < 16; c++) {
        float a = eeB1[c];
        #pragma unroll
        for (int j = 0; j < 16; j++) a = fmaf(xin[j], eeW1[j * 16 + c], a);
        he[c] = fmaxf(a, 0.f);
    }
    const float step = 12.0f / 31.0f;
    const float coeff = -0.5f / (step * step);
    float hr[16];
    #pragma unroll
    for (int c = 0; c < 16; c++) hr[c] = reB1[c];
    #pragma unroll 4
    for (int r = 0; r < 32; r++) {
        float t = d - (float)r * step;
        float rb = __expf(coeff * t * t);
        #pragma unroll
        for (int c = 0; c < 16; c++) hr[c] = fmaf(rb, reW1[r * 16 + c], hr[c]);
    }
    #pragma unroll
    for (int c = 0; c < 16; c++) hr[c] = fmaxf(hr[c], 0.f);
    #pragma unroll
    for (int c = 0; c < 16; c++) {
        float a = eeB2[c] + reB2[c];
        #pragma unroll
        for (int j = 0; j < 16; j++)
            a = fmaf(he[j], eeW2[j * 16 + c], fmaf(hr[j], reW2[j * 16 + c], a));
        g_eattr[e * 16 + c] = a;
    }
}

// ---------------- conv layer: mma.sync split-bf16, per-warp independent ----------------
__global__ void __launch_bounds__(cfg::THREADS, 1)
conv_kernel(const int* __restrict__ ei,
            const float* __restrict__ W1g, const float* __restrict__ B1g,
            const float* __restrict__ W2g, const float* __restrict__ B2g) {
    extern __shared__ char sm[];
    uint4* B2F = (uint4*)(sm + cfg::OFF_B2F);
    uint4* B1F = (uint4*)(sm + cfg::OFF_B1F);
    float* bias2s = (float*)(sm + cfg::OFF_BIAS2);
    float* bias1s = (float*)(sm + cfg::OFF_BIAS1);
    const int tid = threadIdx.x, lane = tid & 31, warp = tid >> 5;
    const int g = lane >> 2, c = lane & 3;

    // ---- pack weights into fragment-order smem (hi/lo split) ----
    for (int t = tid; t < 52 * 4 * 32; t += cfg::THREADS) {
        int nt = t >> 7, rem = t & 127, ks = rem >> 5, ln = rem & 31;
        int gg = ln >> 2, cc = ln & 3;
        int n = nt * 8 + gg, k0 = ks * 16 + 2 * cc;
        uint32_t hx, lx, hy, ly;
        split2(W2g[k0 * 416 + n], W2g[(k0 + 1) * 416 + n], hx, lx);
        split2(W2g[(k0 + 8) * 416 + n], W2g[(k0 + 9) * 416 + n], hy, ly);
        B2F[t] = make_uint4(hx, hy, lx, ly);
    }
    for (int t = tid; t < 8 * 3 * 32; t += cfg::THREADS) {
        int nt = t / 96, rem = t % 96, ks = rem >> 5, ln = rem & 31;
        int gg = ln >> 2, cc = ln & 3;
        int n = nt * 8 + gg, k0 = ks * 16 + 2 * cc;
        uint32_t hx, lx, hy, ly;
        split2(W1g[k0 * 64 + n], W1g[(k0 + 1) * 64 + n], hx, lx);
        split2(W1g[(k0 + 8) * 64 + n], W1g[(k0 + 9) * 64 + n], hy, ly);
        B1F[t] = make_uint4(hx, hy, lx, ly);
    }
    for (int t = tid; t < 416; t += cfg::THREADS) bias2s[t] = B2g[t];
    for (int t = tid; t < 64; t += cfg::THREADS) bias1s[t] = B1g[t];
    __syncthreads();

    float* sl  = (float*)(sm + cfg::OFF_SLAB) + warp * cfg::SLABF;
    float* X0  = sl;          // [16][20]
    float* X1  = sl + 320;    // [16][12]
    float* DOT = sl + 512;    // [16][4]
    float* CR  = sl + 576;    // [16][12]
    float* Y1s = sl + 768;    // [16][3]

    const unsigned FULL = 0xffffffffu;
    const float n0sc = 0.22360679774997896f;   // 1/sqrt(20)
    const float n1sc = 0.20412414523193150f;   // 1/sqrt(24)

    for (int blk = blockIdx.x * cfg::NWARP + warp; blk < cfg::NBLK;
         blk += gridDim.x * cfg::NWARP) {
        const int ebase = blk * 16;

        // ---- stage per-edge data (warp-local) ----
        {   // x0 = h0[dst]: 2 lanes per edge
            int e = lane >> 1, half = lane & 1;
            int dn = ei[cfg::NE + ebase + e];
            const float4* p = (const float4*)(g_h0 + (size_t)dn * 16 + half * 8);
            float4 v0 = p[0], v1 = p[1];
            *(float4*)(X0 + e * 20 + half * 8) = v0;
            *(float4*)(X0 + e * 20 + half * 8 + 4) = v1;
        }
        if (lane < 16) {
            int e = lane, ge = ebase + e;
            int dn = ei[cfg::NE + ge];
            float ya = g_y1[ge * 3 + 0], yb = g_y1[ge * 3 + 1], yc = g_y1[ge * 3 + 2];
            Y1s[e * 3 + 0] = ya; Y1s[e * 3 + 1] = yb; Y1s[e * 3 + 2] = yc;
            float x1r[12];
            #pragma unroll
            for (int q = 0; q < 3; q++)
                ((float4*)x1r)[q] = ((const float4*)(g_h1 + (size_t)dn * 12))[q];
            #pragma unroll
            for (int n = 0; n < 4; n++) {
                float xa = x1r[n*3], xb = x1r[n*3+1], xc = x1r[n*3+2];
                X1[e*12 + n*3 + 0] = xa; X1[e*12 + n*3 + 1] = xb; X1[e*12 + n*3 + 2] = xc;
                DOT[e*4 + n] = (xa*ya + xb*yb + xc*yc) * 0.57735026918962576f;
                CR[e*12 + n*3 + 0] = (xb*yc - xc*yb) * 0.70710678118654752f;
                CR[e*12 + n*3 + 1] = (xc*ya - xa*yc) * 0.70710678118654752f;
                CR[e*12 + n*3 + 2] = (xa*yb - xb*ya) * 0.70710678118654752f;
            }
        }
        __syncwarp();

        // ---- fc1 A-fragments straight from global ----
        const int gx0 = ebase + g, gx1 = gx0 + 8;
        const int sn0 = ei[gx0], sn1 = ei[gx1];
        const int dn0 = ei[cfg::NE + gx0], dn1 = ei[cfg::NE + gx1];
        const float* seg0[3] = { g_eattr + (size_t)gx0 * 16, g_h0 + (size_t)sn0 * 16, g_h0 + (size_t)dn0 * 16 };
        const float* seg1[3] = { g_eattr + (size_t)gx1 * 16, g_h0 + (size_t)sn1 * 16, g_h0 + (size_t)dn1 * 16 };

        uint32_t a1h[3][4], a1l[3][4];
        #pragma unroll
        for (int ks = 0; ks < 3; ks++) {
            float2 r0lo = *(const float2*)(seg0[ks] + 2 * c);
            float2 r0hi = *(const float2*)(seg0[ks] + 2 * c + 8);
            float2 r1lo = *(const float2*)(seg1[ks] + 2 * c);
            float2 r1hi = *(const float2*)(seg1[ks] + 2 * c + 8);
            split2(r0lo.x, r0lo.y, a1h[ks][0], a1l[ks][0]);   // row g,   k-lo
            split2(r1lo.x, r1lo.y, a1h[ks][1], a1l[ks][1]);   // row g+8, k-lo
            split2(r0hi.x, r0hi.y, a1h[ks][2], a1l[ks][2]);   // row g,   k-hi
            split2(r1hi.x, r1hi.y, a1h[ks][3], a1l[ks][3]);   // row g+8, k-hi
        }

        // ---- fc1 GEMM: D1[16,64] ----
        float d1[8][4];
        #pragma unroll
        for (int nt = 0; nt < 8; nt++) { d1[nt][0]=0.f; d1[nt][1]=0.f; d1[nt][2]=0.f; d1[nt][3]=0.f; }
        #pragma unroll
        for (int nt = 0; nt < 8; nt++)
            #pragma unroll
            for (int ks = 0; ks < 3; ks++) {
                uint4 B = B1F[(nt * 3 + ks) * 32 + lane];
                mma16816(d1[nt], a1h[ks], B.x, B.y);
                mma16816(d1[nt], a1h[ks], B.z, B.w);
                mma16816(d1[nt], a1l[ks], B.x, B.y);
            }

        // ---- bias + relu + split -> fc2 A-fragments (register chain, no smem) ----
        uint32_t a2h[4][4], a2l[4][4];
        #pragma unroll
        for (int nt = 0; nt < 8; nt++) {
            float b0 = bias1s[nt * 8 + 2 * c], b1 = bias1s[nt * 8 + 2 * c + 1];
            float v0 = fmaxf(d1[nt][0] + b0, 0.f), v1 = fmaxf(d1[nt][1] + b1, 0.f);
            float v2 = fmaxf(d1[nt][2] + b0, 0.f), v3 = fmaxf(d1[nt][3] + b1, 0.f);
            int ks2 = nt >> 1, sl2 = (nt & 1) * 2;
            split2(v0, v1, a2h[ks2][sl2],     a2l[ks2][sl2]);      // row g
            split2(v2, v3, a2h[ks2][sl2 + 1], a2l[ks2][sl2 + 1]);  // row g+8
        }

        // ---- fc2 + tensor-product contraction, per column-pair ----
        float o0a[2][4];
        #pragma unroll
        for (int r = 0; r < 2; r++) { o0a[r][0]=0.f; o0a[r][1]=0.f; o0a[r][2]=0.f; o0a[r][3]=0.f; }
        float t011p[2][2] = {{0.f,0.f},{0.f,0.f}};
        float o1p[2][2][3];
        #pragma unroll
        for (int r = 0; r < 2; r++)
            #pragma unroll
            for (int s = 0; s < 2; s++) { o1p[r][s][0]=0.f; o1p[r][s][1]=0.f; o1p[r][s][2]=0.f; }
        const int e0 = g, e1 = g + 8;

        #define FC2_PAIR(j, dA, dB)                                             \
            float dA[4] = {0.f,0.f,0.f,0.f}, dB[4] = {0.f,0.f,0.f,0.f};         \
            {   int ntA = 2 * (j);                                              \
                _Pragma("unroll")                                               \
                for (int ks = 0; ks < 4; ks++) {                                \
                    uint4 BA = B2F[(ntA * 4 + ks) * 32 + lane];                 \
                    mma16816(dA, a2h[ks], BA.x, BA.y);                          \
                    mma16816(dA, a2h[ks], BA.z, BA.w);                          \
                    mma16816(dA, a2l[ks], BA.x, BA.y);                          \
                    uint4 BB = B2F[((ntA + 1) * 4 + ks) * 32 + lane];           \
                    mma16816(dB, a2h[ks], BB.x, BB.y);                          \
                    mma16816(dB, a2h[ks], BB.z, BB.w);                          \
                    mma16816(dB, a2l[ks], BB.x, BB.y);                          \
                } }                                                             \
            float bA0 = bias2s[16*(j) + 2*c],     bA1 = bias2s[16*(j) + 2*c + 1]; \
            float bB0 = bias2s[16*(j) + 8 + 2*c], bB1 = bias2s[16*(j) + 9 + 2*c]; \
            float wA0 = dA[0]+bA0, wA1 = dA[1]+bA1, wA2 = dA[2]+bA0, wA3 = dA[3]+bA1; \
            float wB0 = dB[0]+bB0, wB1 = dB[1]+bB1, wB2 = dB[2]+bB0, wB3 = dB[3]+bB1;

        // pairs 0..15: w00  (o0 += x0[n=j] * w)
        for (int j = 0; j < 16; j++) {
            FC2_PAIR(j, dA, dB);
            float xa = X0[e0 * 20 + j], xb = X0[e1 * 20 + j];
            o0a[0][0] = fmaf(xa, wA0, o0a[0][0]); o0a[0][1] = fmaf(xa, wA1, o0a[0][1]);
            o0a[0][2] = fmaf(xa, wB0, o0a[0][2]); o0a[0][3] = fmaf(xa, wB1, o0a[0][3]);
            o0a[1][0] = fmaf(xb, wA2, o0a[1][0]); o0a[1][1] = fmaf(xb, wA3, o0a[1][1]);
            o0a[1][2] = fmaf(xb, wB2, o0a[1][2]); o0a[1][3] = fmaf(xb, wB3, o0a[1][3]);
        }
        // pairs 16..19: w011 (t011[o] += x0[n] * w)
        for (int j = 16; j < 20; j++) {
            FC2_PAIR(j, dA, dB);
            int nA = 4 * (j - 16) + (c >> 1), nB = nA + 2;
            float xa0 = X0[e0*20 + nA], xb0 = X0[e0*20 + nB];
            float xa1 = X0[e1*20 + nA], xb1 = X0[e1*20 + nB];
            t011p[0][0] += xa0 * wA0 + xb0 * wB0;
            t011p[0][1] += xa0 * wA1 + xb0 * wB1;
            t011p[1][0] += xa1 * wA2 + xb1 * wB2;
            t011p[1][1] += xa1 * wA3 + xb1 * wB3;
        }
        // pair 20: w101 (o1[o][m] += x1[n][m] * w)
        {
            FC2_PAIR(20, dA, dB);
            int nA = c >> 1, nB = nA + 2;
            #pragma unroll
            for (int m = 0; m < 3; m++) {
                float xa0 = X1[e0*12 + nA*3 + m], xb0 = X1[e0*12 + nB*3 + m];
                float xa1 = X1[e1*12 + nA*3 + m], xb1 = X1[e1*12 + nB*3 + m];
                o1p[0][0][m] += xa0 * wA0 + xb0 * wB0;
                o1p[0][1][m] += xa0 * wA1 + xb0 * wB1;
                o1p[1][0][m] += xa1 * wA2 + xb1 * wB2;
                o1p[1][1][m] += xa1 * wA3 + xb1 * wB3;
            }
        }
        // pairs 21..24: w110 (o0 += dot[n=j-21] * w)
        for (int j = 21; j < 25; j++) {
            FC2_PAIR(j, dA, dB);
            float da = DOT[e0*4 + (j - 21)], db = DOT[e1*4 + (j - 21)];
            o0a[0][0] = fmaf(da, wA0, o0a[0][0]); o0a[0][1] = fmaf(da, wA1, o0a[0][1]);
            o0a[0][2] = fmaf(da, wB0, o0a[0][2]); o0a[0][3] = fmaf(da, wB1, o0a[0][3]);
            o0a[1][0] = fmaf(db, wA2, o0a[1][0]); o0a[1][1] = fmaf(db, wA3, o0a[1][1]);
            o0a[1][2] = fmaf(db, wB2, o0a[1][2]); o0a[1][3] = fmaf(db, wB3, o0a[1][3]);
        }
        // pair 25: w111 (o1 += cr[n][m] * w)
        {
            FC2_PAIR(25, dA, dB);
            int nA = c >> 1, nB = nA + 2;
            #pragma unroll
            for (int m = 0; m < 3; m++) {
                float xa0 = CR[e0*12 + nA*3 + m], xb0 = CR[e0*12 + nB*3 + m];
                float xa1 = CR[e1*12 + nA*3 + m], xb1 = CR[e1*12 + nB*3 + m];
                o1p[0][0][m] += xa0 * wA0 + xb0 * wB0;
                o1p[0][1][m] += xa0 * wA1 + xb0 * wB1;
                o1p[1][0][m] += xa1 * wA2 + xb1 * wB2;
                o1p[1][1][m] += xa1 * wA3 + xb1 * wB3;
            }
        }
        #undef FC2_PAIR

        // ---- l=0 scatter (no reduction needed: thread owns its 4 o-columns) ----
        #pragma unroll
        for (int r = 0; r < 2; r++) {
            int sn = r ? sn1 : sn0;
            #pragma unroll
            for (int s = 0; s < 4; s++) {
                int o = (s < 2) ? (2 * c + s) : (8 + 2 * c + (s - 2));
                atomicAdd(&g_acc0[sn * 16 + o], n0sc * o0a[r][s]);
            }
        }
        // ---- l=1: reduce across c<->c^2, add t011*y1, scatter ----
        #pragma unroll
        for (int r = 0; r < 2; r++)
            #pragma unroll
            for (int s = 0; s < 2; s++) {
                t011p[r][s] += __shfl_xor_sync(FULL, t011p[r][s], 2);
                #pragma unroll
                for (int m = 0; m < 3; m++)
                    o1p[r][s][m] += __shfl_xor_sync(FULL, o1p[r][s][m], 2);
            }
        if (c < 2) {
            #pragma unroll
            for (int r = 0; r < 2; r++) {
                int e = r ? e1 : e0;
                int sn = r ? sn1 : sn0;
                #pragma unroll
                for (int s = 0; s < 2; s++) {
                    int o = 2 * c + s;
                    float t = t011p[r][s];
                    #pragma unroll
                    for (int m = 0; m < 3; m++) {
                        float val = o1p[r][s][m] + t * Y1s[e * 3 + m];
                        atomicAdd(&g_acc1[sn * 12 + o * 3 + m], n1sc * val);
                    }
                }
            }
        }
        __syncwarp();
    }
}

// ---------------- scatter-mean residual update ----------------
__global__ void update_kernel() {
    int i = blockIdx.x * blockDim.x + threadIdx.x;
    if (i < cfg::NN * 16) {
        int n = i >> 4;
        float inv = 1.f / fmaxf(g_cnt[n], 1.f);
        g_h0[i] += g_acc0[i] * inv;
        g_acc0[i] = 0.f;
    }
    if (i < cfg::NN * 12) {
        int n = i / 12;
        float inv = 1.f / fmaxf(g_cnt[n], 1.f);
        g_h1[i] += g_acc1[i] * inv;
        g_acc1[i] = 0.f;
    }
}

// ---------------- final update + o3.Linear + sorter ----------------
__global__ void final_kernel(float* __restrict__ out,
                             const float* __restrict__ lin0, const float* __restrict__ lin1) {
    int n = blockIdx.x * blockDim.x + threadIdx.x;
    if (n >= cfg::NN) return;
    float inv = 1.f / fmaxf(g_cnt[n], 1.f);
    float h0f[16];
    #pragma unroll
    for (int s = 0; s < 16; s++) h0f[s] = g_h0[n * 16 + s] + g_acc0[n * 16 + s] * inv;
    float h1f[12];
    #pragma unroll
    for (int s = 0; s < 12; s++) h1f[s] = g_h1[n * 12 + s] + g_acc1[n * 12 + s] * inv;
    float* o = out + (size_t)n * 128;
    #pragma unroll 4
    for (int cc = 0; cc < 32; cc++) {
        float f0 = 0.f;
        #pragma unroll
        for (int s = 0; s < 16; s++) f0 = fmaf(h0f[s], lin0[s * 32 + cc], f0);
        o[4 * cc] = 0.25f * f0;
        #pragma unroll
        for (int m = 0; m < 3; m++) {
            float f1 = 0.f;
            #pragma unroll
            for (int v = 0; v < 4; v++) f1 = fmaf(h1f[v * 3 + m], lin1[v * 32 + cc], f1);
            o[4 * cc + 1 + m] = 0.5f * f1;
        }
    }
}

// ---------------- launch ----------------
extern "C" void kernel_launch(void* const* d_in, const int* in_sizes, int n_in,
                              void* d_out, int out_size) {
    const float* pos          = (const float*)d_in[0];
    const float* node_feats   = (const float*)d_in[1];
    const float* edge_attr_in = (const float*)d_in[2];
    const int*   edge_index   = (const int*)d_in[3];
    const float* enc_W  = (const float*)d_in[4];
    const float* enc_b  = (const float*)d_in[5];
    const float* ne_W1  = (const float*)d_in[6];
    const float* ne_b1  = (const float*)d_in[7];
    const float* ne_W2  = (const float*)d_in[8];
    const float* ne_b2  = (const float*)d_in[9];
    const float* ee_W1  = (const float*)d_in[10];
    const float* ee_b1  = (const float*)d_in[11];
    const float* ee_W2  = (const float*)d_in[12];
    const float* ee_b2  = (const float*)d_in[13];
    const float* re_W1  = (const float*)d_in[14];
    const float* re_b1  = (const float*)d_in[15];
    const float* re_W2  = (const float*)d_in[16];
    const float* re_b2  = (const float*)d_in[17];
    const float* fc1_W  = (const float*)d_in[18];   // [2,48,64]
    const float* fc1_b  = (const float*)d_in[19];   // [2,64]
    const float* fc2_W  = (const float*)d_in[20];   // [2,64,416]
    const float* fc2_b  = (const float*)d_in[21];   // [2,416]
    const float* lin0_W = (const float*)d_in[22];
    const float* lin1_W = (const float*)d_in[23];
    float* out = (float*)d_out;

    int dev = 0;
    cudaGetDevice(&dev);
    int nsm = 148;
    cudaDeviceGetAttribute(&nsm, cudaDevAttrMultiProcessorCount, dev);
    cudaFuncSetAttribute(conv_kernel, cudaFuncAttributeMaxDynamicSharedMemorySize, cfg::SMEM_BYTES);

    zero_kernel<<<256, 256>>>();
    node_init_kernel<<<(cfg::NN + 127) / 128, 128>>>(node_feats, enc_W, enc_b,
                                                     ne_W1, ne_b1, ne_W2, ne_b2);
    edge_init_kernel<<<(cfg::NE + 127) / 128, 128>>>(pos, edge_attr_in, edge_index,
                                                     ee_W1, ee_b1, ee_W2, ee_b2,
                                                     re_W1, re_b1, re_W2, re_b2);
    // layer 0
    conv_kernel<<<nsm, cfg::THREADS, cfg::SMEM_BYTES>>>(edge_index,
        fc1_W, fc1_b, fc2_W, fc2_b);
    update_kernel<<<(cfg::NN * 16 + 255) / 256, 256>>>();
    // layer 1
    conv_kernel<<<nsm, cfg::THREADS, cfg::SMEM_BYTES>>>(edge_index,
        fc1_W + 48 * 64, fc1_b + 64, fc2_W + 64 * 416, fc2_b + 416);
    // final
    final_kernel<<<(cfg::NN + 127) / 128, 128>>>(out, lin0_W, lin1_W);
}

// round 10
// speedup vs baseline: 2.7090x; 1.0182x over previous
#include <cuda_runtime.h>
#include <cuda_bf16.h>
#include <cstdint>

// ---------------- static config ----------------
namespace cfg {
constexpr int NN = 10000;
constexpr int NE = 128000;
constexpr int NWARP = 8;
constexpr int THREADS = NWARP * 32;     // 256
constexpr int NBLK = NE / 32;           // 4000 32-edge blocks (2 M-tiles each)

// smem byte offsets
constexpr int OFF_B2F   = 0;            // fc2 weight frags: [52 nt][4 ks][32 lane] uint4 = 106496B
constexpr int OFF_B1F   = 106496;       // fc1 weight frags: [8 nt][3 ks][32 lane] uint4 = 12288B
constexpr int OFF_BIAS2 = 118784;       // 416 f32
constexpr int OFF_BIAS1 = 120448;       // 64 f32
constexpr int OFF_SLAB  = 120704;       // per-warp slabs: 1664 f32 each
constexpr int SLABF     = 1664;
constexpr int SMEM_BYTES = OFF_SLAB + NWARP * SLABF * 4;   // 173952
}

// ---------------- helpers ----------------
__device__ __forceinline__ void split2(float x, float y, uint32_t& h, uint32_t& l) {
    __nv_bfloat162 hb = __floats2bfloat162_rn(x, y);        // x -> low, y -> high
    h = *(const uint32_t*)&hb;
    float rx = x - __bfloat162float(hb.x);
    float ry = y - __bfloat162float(hb.y);
    __nv_bfloat162 lb = __floats2bfloat162_rn(rx, ry);
    l = *(const uint32_t*)&lb;
}
__device__ __forceinline__ void mma16816(float (&d)[4], const uint32_t (&a)[4],
                                         uint32_t b0, uint32_t b1) {
    asm volatile(
        "mma.sync.aligned.m16n8k16.row.col.f32.bf16.bf16.f32 "
        "{%0,%1,%2,%3}, {%4,%5,%6,%7}, {%8,%9}, {%0,%1,%2,%3};"
        : "+f"(d[0]), "+f"(d[1]), "+f"(d[2]), "+f"(d[3])
        : "r"(a[0]), "r"(a[1]), "r"(a[2]), "r"(a[3]), "r"(b0), "r"(b1));
}

// ---------------- device scratch ----------------
__device__ float g_h0[cfg::NN * 16];
__device__ float g_h1[cfg::NN * 12];
__device__ float g_acc0[cfg::NN * 16];
__device__ float g_acc1[cfg::NN * 12];
__device__ float g_cnt[cfg::NN];
__device__ float g_eattr[cfg::NE * 16];
__device__ float g_y1[cfg::NE * 3];

// ---------------- zero scratch ----------------
__global__ void zero_kernel() {
    int i = blockIdx.x * blockDim.x + threadIdx.x;
    int stride = gridDim.x * blockDim.x;
    for (int t = i; t < cfg::NN * 16; t += stride) g_acc0[t] = 0.f;
    for (int t = i; t < cfg::NN * 12; t += stride) { g_acc1[t] = 0.f; g_h1[t] = 0.f; }
    for (int t = i; t < cfg::NN; t += stride) g_cnt[t] = 0.f;
}

// ---------------- node encoder + node_embedding MLP ----------------
__global__ void node_init_kernel(const float* __restrict__ nf,
                                 const float* __restrict__ encW, const float* __restrict__ encB,
                                 const float* __restrict__ W1, const float* __restrict__ B1,
                                 const float* __restrict__ W2, const float* __restrict__ B2) {
    int n = blockIdx.x * blockDim.x + threadIdx.x;
    if (n >= cfg::NN) return;
    float enc[16];
    #pragma unroll
    for (int c = 0; c < 16; c++) enc[c] = encB[c];
    for (int f = 0; f < 64; f++) {
        float v = nf[n * 64 + f];
        #pragma unroll
        for (int c = 0; c < 16; c++) enc[c] = fmaf(v, encW[f * 16 + c], enc[c]);
    }
    float t[16];
    #pragma unroll
    for (int c = 0; c < 16; c++) {
        float a = B1[c];
        #pragma unroll
        for (int j = 0; j < 16; j++) a = fmaf(enc[j], W1[j * 16 + c], a);
        t[c] = fmaxf(a, 0.f);
    }
    #pragma unroll
    for (int c = 0; c < 16; c++) {
        float a = B2[c];
        #pragma unroll
        for (int j = 0; j < 16; j++) a = fmaf(t[j], W2[j * 16 + c], a);
        g_h0[n * 16 + c] = a;
    }
}

// ---------------- per-edge init ----------------
__global__ void edge_init_kernel(const float* __restrict__ pos,
                                 const float* __restrict__ eain, const int* __restrict__ ei,
                                 const float* __restrict__ eeW1, const float* __restrict__ eeB1,
                                 const float* __restrict__ eeW2, const float* __restrict__ eeB2,
                                 const float* __restrict__ reW1, const float* __restrict__ reB1,
                                 const float* __restrict__ reW2, const float* __restrict__ reB2) {
    int e = blockIdx.x * blockDim.x + threadIdx.x;
    if (e >= cfg::NE) return;
    int sn = ei[e], dn = ei[cfg::NE + e];
    float vx = pos[sn * 3 + 0] - pos[dn * 3 + 0];
    float vy = pos[sn * 3 + 1] - pos[dn * 3 + 1];
    float vz = pos[sn * 3 + 2] - pos[dn * 3 + 2];
    float d = sqrtf(vx * vx + vy * vy + vz * vz);
    float dmx = fmaxf(d, 1e-9f);
    float s = 1.7320508075688772f / dmx;
    g_y1[e * 3 + 0] = s * vx;
    g_y1[e * 3 + 1] = s * vy;
    g_y1[e * 3 + 2] = s * vz;
    atomicAdd(&g_cnt[sn], 1.f);

    float xin[16];
    #pragma unroll
    for (int j = 0; j < 16; j++) xin[j] = eain[e * 16 + j];
    float he[16];
    #pragma unroll
    for (int c = 0; c < 16; c++) {
        float a = eeB1[c];
        #pragma unroll
        for (int j = 0; j < 16; j++) a = fmaf(xin[j], eeW1[j * 16 + c], a);
        he[c] = fmaxf(a, 0.f);
    }
    const float step = 12.0f / 31.0f;
    const float coeff = -0.5f / (step * step);
    float hr[16];
    #pragma unroll
    for (int c = 0; c < 16; c++) hr[c] = reB1[c];
    #pragma unroll 4
    for (int r = 0; r < 32; r++) {
        float t = d - (float)r * step;
        float rb = __expf(coeff * t * t);
        #pragma unroll
        for (int c = 0; c < 16; c++) hr[c] = fmaf(rb, reW1[r * 16 + c], hr[c]);
    }
    #pragma unroll
    for (int c = 0; c < 16; c++) hr[c] = fmaxf(hr[c], 0.f);
    #pragma unroll
    for (int c = 0; c < 16; c++) {
        float a = eeB2[c] + reB2[c];
        #pragma unroll
        for (int j = 0; j < 16; j++)
            a = fmaf(he[j], eeW2[j * 16 + c], fmaf(hr[j], reW2[j * 16 + c], a));
        g_eattr[e * 16 + c] = a;
    }
}

// ---------------- conv layer: mma.sync split-bf16, 2 M-tiles per warp ----------------
__global__ void __launch_bounds__(cfg::THREADS, 1)
conv_kernel(const int* __restrict__ ei,
            const float* __restrict__ W1g, const float* __restrict__ B1g,
            const float* __restrict__ W2g, const float* __restrict__ B2g) {
    extern __shared__ char sm[];
    uint4* B2F = (uint4*)(sm + cfg::OFF_B2F);
    uint4* B1F = (uint4*)(sm + cfg::OFF_B1F);
    float* bias2s = (float*)(sm + cfg::OFF_BIAS2);
    float* bias1s = (float*)(sm + cfg::OFF_BIAS1);
    const int tid = threadIdx.x, lane = tid & 31, warp = tid >> 5;
    const int g = lane >> 2, c = lane & 3;

    // ---- pack weights into fragment-order smem (hi/lo split) ----
    for (int t = tid; t < 52 * 4 * 32; t += cfg::THREADS) {
        int nt = t >> 7, rem = t & 127, ks = rem >> 5, ln = rem & 31;
        int gg = ln >> 2, cc = ln & 3;
        int n = nt * 8 + gg, k0 = ks * 16 + 2 * cc;
        uint32_t hx, lx, hy, ly;
        split2(W2g[k0 * 416 + n], W2g[(k0 + 1) * 416 + n], hx, lx);
        split2(W2g[(k0 + 8) * 416 + n], W2g[(k0 + 9) * 416 + n], hy, ly);
        B2F[t] = make_uint4(hx, hy, lx, ly);
    }
    for (int t = tid; t < 8 * 3 * 32; t += cfg::THREADS) {
        int nt = t / 96, rem = t % 96, ks = rem >> 5, ln = rem & 31;
        int gg = ln >> 2, cc = ln & 3;
        int n = nt * 8 + gg, k0 = ks * 16 + 2 * cc;
        uint32_t hx, lx, hy, ly;
        split2(W1g[k0 * 64 + n], W1g[(k0 + 1) * 64 + n], hx, lx);
        split2(W1g[(k0 + 8) * 64 + n], W1g[(k0 + 9) * 64 + n], hy, ly);
        B1F[t] = make_uint4(hx, hy, lx, ly);
    }
    for (int t = tid; t < 416; t += cfg::THREADS) bias2s[t] = B2g[t];
    for (int t = tid; t < 64; t += cfg::THREADS) bias1s[t] = B1g[t];
    __syncthreads();

    float* sl  = (float*)(sm + cfg::OFF_SLAB) + warp * cfg::SLABF;
    float* X0  = sl;           // [32][20]
    float* X1  = sl + 640;     // [32][12]
    float* DOT = sl + 1024;    // [32][4]
    float* CR  = sl + 1152;    // [32][12]
    float* Y1s = sl + 1536;    // [32][3]

    const unsigned FULL = 0xffffffffu;
    const float n0sc = 0.22360679774997896f;   // 1/sqrt(20)
    const float n1sc = 0.20412414523193150f;   // 1/sqrt(24)

    for (int blk = blockIdx.x * cfg::NWARP + warp; blk < cfg::NBLK;
         blk += gridDim.x * cfg::NWARP) {
        const int ebase = blk * 32;

        // ---- stage per-edge data: each lane owns one of 32 edges ----
        {
            int e = lane, ge = ebase + e;
            int dn = ei[cfg::NE + ge];
            const float4* p = (const float4*)(g_h0 + (size_t)dn * 16);
            *(float4*)(X0 + e * 20 + 0)  = p[0];
            *(float4*)(X0 + e * 20 + 4)  = p[1];
            *(float4*)(X0 + e * 20 + 8)  = p[2];
            *(float4*)(X0 + e * 20 + 12) = p[3];
            float ya = g_y1[ge * 3 + 0], yb = g_y1[ge * 3 + 1], yc = g_y1[ge * 3 + 2];
            Y1s[e * 3 + 0] = ya; Y1s[e * 3 + 1] = yb; Y1s[e * 3 + 2] = yc;
            float x1r[12];
            #pragma unroll
            for (int q = 0; q < 3; q++)
                ((float4*)x1r)[q] = ((const float4*)(g_h1 + (size_t)dn * 12))[q];
            #pragma unroll
            for (int n = 0; n < 4; n++) {
                float xa = x1r[n*3], xb = x1r[n*3+1], xc = x1r[n*3+2];
                X1[e*12 + n*3 + 0] = xa; X1[e*12 + n*3 + 1] = xb; X1[e*12 + n*3 + 2] = xc;
                DOT[e*4 + n] = (xa*ya + xb*yb + xc*yc) * 0.57735026918962576f;
                CR[e*12 + n*3 + 0] = (xb*yc - xc*yb) * 0.70710678118654752f;
                CR[e*12 + n*3 + 1] = (xc*ya - xa*yc) * 0.70710678118654752f;
                CR[e*12 + n*3 + 2] = (xa*yb - xb*ya) * 0.70710678118654752f;
            }
        }
        __syncwarp();

        // ---- fc1 per tile -> fc2 A-fragments (register chain) ----
        uint32_t a2h[2][4][4], a2l[2][4][4];
        #pragma unroll
        for (int t = 0; t < 2; t++) {
            const int gx0 = ebase + t * 16 + g, gx1 = gx0 + 8;
            const int sn0 = ei[gx0], sn1 = ei[gx1];
            const int dn0 = ei[cfg::NE + gx0], dn1 = ei[cfg::NE + gx1];
            const float* seg0[3] = { g_eattr + (size_t)gx0 * 16, g_h0 + (size_t)sn0 * 16, g_h0 + (size_t)dn0 * 16 };
            const float* seg1[3] = { g_eattr + (size_t)gx1 * 16, g_h0 + (size_t)sn1 * 16, g_h0 + (size_t)dn1 * 16 };

            uint32_t a1h[3][4], a1l[3][4];
            #pragma unroll
            for (int ks = 0; ks < 3; ks++) {
                float2 r0lo = *(const float2*)(seg0[ks] + 2 * c);
                float2 r0hi = *(const float2*)(seg0[ks] + 2 * c + 8);
                float2 r1lo = *(const float2*)(seg1[ks] + 2 * c);
                float2 r1hi = *(const float2*)(seg1[ks] + 2 * c + 8);
                split2(r0lo.x, r0lo.y, a1h[ks][0], a1l[ks][0]);
                split2(r1lo.x, r1lo.y, a1h[ks][1], a1l[ks][1]);
                split2(r0hi.x, r0hi.y, a1h[ks][2], a1l[ks][2]);
                split2(r1hi.x, r1hi.y, a1h[ks][3], a1l[ks][3]);
            }
            float d1[8][4];
            #pragma unroll
            for (int nt = 0; nt < 8; nt++) { d1[nt][0]=0.f; d1[nt][1]=0.f; d1[nt][2]=0.f; d1[nt][3]=0.f; }
            #pragma unroll
            for (int nt = 0; nt < 8; nt++)
                #pragma unroll
                for (int ks = 0; ks < 3; ks++) {
                    uint4 B = B1F[(nt * 3 + ks) * 32 + lane];
                    mma16816(d1[nt], a1h[ks], B.x, B.y);
                    mma16816(d1[nt], a1h[ks], B.z, B.w);
                    mma16816(d1[nt], a1l[ks], B.x, B.y);
                }
            #pragma unroll
            for (int nt = 0; nt < 8; nt++) {
                float b0 = bias1s[nt * 8 + 2 * c], b1 = bias1s[nt * 8 + 2 * c + 1];
                float v0 = fmaxf(d1[nt][0] + b0, 0.f), v1 = fmaxf(d1[nt][1] + b1, 0.f);
                float v2 = fmaxf(d1[nt][2] + b0, 0.f), v3 = fmaxf(d1[nt][3] + b1, 0.f);
                int ks2 = nt >> 1, sl2 = (nt & 1) * 2;
                split2(v0, v1, a2h[t][ks2][sl2],     a2l[t][ks2][sl2]);
                split2(v2, v3, a2h[t][ks2][sl2 + 1], a2l[t][ks2][sl2 + 1]);
            }
        }

        // ---- fc2 + tensor-product contraction, per column-pair, both tiles ----
        float o0a[2][2][4];
        #pragma unroll
        for (int t = 0; t < 2; t++)
            #pragma unroll
            for (int r = 0; r < 2; r++) { o0a[t][r][0]=0.f; o0a[t][r][1]=0.f; o0a[t][r][2]=0.f; o0a[t][r][3]=0.f; }
        float t011p[2][2][2] = {{{0.f,0.f},{0.f,0.f}},{{0.f,0.f},{0.f,0.f}}};
        float o1p[2][2][2][3];
        #pragma unroll
        for (int t = 0; t < 2; t++)
            #pragma unroll
            for (int r = 0; r < 2; r++)
                #pragma unroll
                for (int s = 0; s < 2; s++) { o1p[t][r][s][0]=0.f; o1p[t][r][s][1]=0.f; o1p[t][r][s][2]=0.f; }

        #define FC2_PAIR(j, dA, dB)                                             \
            float dA[2][4] = {{0.f,0.f,0.f,0.f},{0.f,0.f,0.f,0.f}};             \
            float dB[2][4] = {{0.f,0.f,0.f,0.f},{0.f,0.f,0.f,0.f}};             \
            {   int ntA = 2 * (j);                                              \
                _Pragma("unroll")                                               \
                for (int ks = 0; ks < 4; ks++) {                                \
                    uint4 BA = B2F[(ntA * 4 + ks) * 32 + lane];                 \
                    uint4 BB = B2F[((ntA + 1) * 4 + ks) * 32 + lane];           \
                    _Pragma("unroll")                                           \
                    for (int t = 0; t < 2; t++) {                               \
                        mma16816(dA[t], a2h[t][ks], BA.x, BA.y);                \
                        mma16816(dA[t], a2h[t][ks], BA.z, BA.w);                \
                        mma16816(dA[t], a2l[t][ks], BA.x, BA.y);                \
                        mma16816(dB[t], a2h[t][ks], BB.x, BB.y);                \
                        mma16816(dB[t], a2h[t][ks], BB.z, BB.w);                \
                        mma16816(dB[t], a2l[t][ks], BB.x, BB.y);                \
                    }                                                           \
                } }                                                             \
            {   float bA0 = bias2s[16*(j) + 2*c],     bA1 = bias2s[16*(j) + 2*c + 1]; \
                float bB0 = bias2s[16*(j) + 8 + 2*c], bB1 = bias2s[16*(j) + 9 + 2*c]; \
                _Pragma("unroll")                                               \
                for (int t = 0; t < 2; t++) {                                   \
                    dA[t][0] += bA0; dA[t][1] += bA1; dA[t][2] += bA0; dA[t][3] += bA1; \
                    dB[t][0] += bB0; dB[t][1] += bB1; dB[t][2] += bB0; dB[t][3] += bB1; \
                } }

        // pairs 0..15: w00  (o0 += x0[n=j] * w)
        for (int j = 0; j < 16; j++) {
            FC2_PAIR(j, dA, dB);
            #pragma unroll
            for (int t = 0; t < 2; t++) {
                int e0 = t * 16 + g, e1 = e0 + 8;
                float xa = X0[e0 * 20 + j], xb = X0[e1 * 20 + j];
                o0a[t][0][0] = fmaf(xa, dA[t][0], o0a[t][0][0]); o0a[t][0][1] = fmaf(xa, dA[t][1], o0a[t][0][1]);
                o0a[t][0][2] = fmaf(xa, dB[t][0], o0a[t][0][2]); o0a[t][0][3] = fmaf(xa, dB[t][1], o0a[t][0][3]);
                o0a[t][1][0] = fmaf(xb, dA[t][2], o0a[t][1][0]); o0a[t][1][1] = fmaf(xb, dA[t][3], o0a[t][1][1]);
                o0a[t][1][2] = fmaf(xb, dB[t][2], o0a[t][1][2]); o0a[t][1][3] = fmaf(xb, dB[t][3], o0a[t][1][3]);
            }
        }
        // pairs 16..19: w011 (t011[o] += x0[n] * w)
        for (int j = 16; j < 20; j++) {
            FC2_PAIR(j, dA, dB);
            int nA = 4 * (j - 16) + (c >> 1), nB = nA + 2;
            #pragma unroll
            for (int t = 0; t < 2; t++) {
                int e0 = t * 16 + g, e1 = e0 + 8;
                float xa0 = X0[e0*20 + nA], xb0 = X0[e0*20 + nB];
                float xa1 = X0[e1*20 + nA], xb1 = X0[e1*20 + nB];
                t011p[t][0][0] += xa0 * dA[t][0] + xb0 * dB[t][0];
                t011p[t][0][1] += xa0 * dA[t][1] + xb0 * dB[t][1];
                t011p[t][1][0] += xa1 * dA[t][2] + xb1 * dB[t][2];
                t011p[t][1][1] += xa1 * dA[t][3] + xb1 * dB[t][3];
            }
        }
        // pair 20: w101 (o1[o][m] += x1[n][m] * w)
        {
            FC2_PAIR(20, dA, dB);
            int nA = c >> 1, nB = nA + 2;
            #pragma unroll
            for (int t = 0; t < 2; t++) {
                int e0 = t * 16 + g, e1 = e0 + 8;
                #pragma unroll
                for (int m = 0; m < 3; m++) {
                    float xa0 = X1[e0*12 + nA*3 + m], xb0 = X1[e0*12 + nB*3 + m];
                    float xa1 = X1[e1*12 + nA*3 + m], xb1 = X1[e1*12 + nB*3 + m];
                    o1p[t][0][0][m] += xa0 * dA[t][0] + xb0 * dB[t][0];
                    o1p[t][0][1][m] += xa0 * dA[t][1] + xb0 * dB[t][1];
                    o1p[t][1][0][m] += xa1 * dA[t][2] + xb1 * dB[t][2];
                    o1p[t][1][1][m] += xa1 * dA[t][3] + xb1 * dB[t][3];
                }
            }
        }
        // pairs 21..24: w110 (o0 += dot[n=j-21] * w)
        for (int j = 21; j < 25; j++) {
            FC2_PAIR(j, dA, dB);
            #pragma unroll
            for (int t = 0; t < 2; t++) {
                int e0 = t * 16 + g, e1 = e0 + 8;
                float da = DOT[e0*4 + (j - 21)], db = DOT[e1*4 + (j - 21)];
                o0a[t][0][0] = fmaf(da, dA[t][0], o0a[t][0][0]); o0a[t][0][1] = fmaf(da, dA[t][1], o0a[t][0][1]);
                o0a[t][0][2] = fmaf(da, dB[t][0], o0a[t][0][2]); o0a[t][0][3] = fmaf(da, dB[t][1], o0a[t][0][3]);
                o0a[t][1][0] = fmaf(db, dA[t][2], o0a[t][1][0]); o0a[t][1][1] = fmaf(db, dA[t][3], o0a[t][1][1]);
                o0a[t][1][2] = fmaf(db, dB[t][2], o0a[t][1][2]); o0a[t][1][3] = fmaf(db, dB[t][3], o0a[t][1][3]);
            }
        }
        // pair 25: w111 (o1 += cr[n][m] * w)
        {
            FC2_PAIR(25, dA, dB);
            int nA = c >> 1, nB = nA + 2;
            #pragma unroll
            for (int t = 0; t < 2; t++) {
                int e0 = t * 16 + g, e1 = e0 + 8;
                #pragma unroll
                for (int m = 0; m < 3; m++) {
                    float xa0 = CR[e0*12 + nA*3 + m], xb0 = CR[e0*12 + nB*3 + m];
                    float xa1 = CR[e1*12 + nA*3 + m], xb1 = CR[e1*12 + nB*3 + m];
                    o1p[t][0][0][m] += xa0 * dA[t][0] + xb0 * dB[t][0];
                    o1p[t][0][1][m] += xa0 * dA[t][1] + xb0 * dB[t][1];
                    o1p[t][1][0][m] += xa1 * dA[t][2] + xb1 * dB[t][2];
                    o1p[t][1][1][m] += xa1 * dA[t][3] + xb1 * dB[t][3];
                }
            }
        }
        #undef FC2_PAIR

        // ---- l=0 scatter ----
        #pragma unroll
        for (int t = 0; t < 2; t++)
            #pragma unroll
            for (int r = 0; r < 2; r++) {
                int sn = ei[ebase + t * 16 + g + r * 8];
                #pragma unroll
                for (int s = 0; s < 4; s++) {
                    int o = (s < 2) ? (2 * c + s) : (8 + 2 * c + (s - 2));
                    atomicAdd(&g_acc0[sn * 16 + o], n0sc * o0a[t][r][s]);
                }
            }
        // ---- l=1: reduce across c<->c^2, add t011*y1, scatter ----
        #pragma unroll
        for (int t = 0; t < 2; t++)
            #pragma unroll
            for (int r = 0; r < 2; r++)
                #pragma unroll
                for (int s = 0; s < 2; s++) {
                    t011p[t][r][s] += __shfl_xor_sync(FULL, t011p[t][r][s], 2);
                    #pragma unroll
                    for (int m = 0; m < 3; m++)
                        o1p[t][r][s][m] += __shfl_xor_sync(FULL, o1p[t][r][s][m], 2);
                }
        if (c < 2) {
            #pragma unroll
            for (int t = 0; t < 2; t++)
                #pragma unroll
                for (int r = 0; r < 2; r++) {
                    int e = t * 16 + g + r * 8;
                    int sn = ei[ebase + e];
                    #pragma unroll
                    for (int s = 0; s < 2; s++) {
                        int o = 2 * c + s;
                        float tt = t011p[t][r][s];
                        #pragma unroll
                        for (int m = 0; m < 3; m++) {
                            float val = o1p[t][r][s][m] + tt * Y1s[e * 3 + m];
                            atomicAdd(&g_acc1[sn * 12 + o * 3 + m], n1sc * val);
                        }
                    }
                }
        }
        __syncwarp();
    }
}

// ---------------- scatter-mean residual update ----------------
__global__ void update_kernel() {
    int i = blockIdx.x * blockDim.x + threadIdx.x;
    if (i < cfg::NN * 16) {
        int n = i >> 4;
        float inv = 1.f / fmaxf(g_cnt[n], 1.f);
        g_h0[i] += g_acc0[i] * inv;
        g_acc0[i] = 0.f;
    }
    if (i < cfg::NN * 12) {
        int n = i / 12;
        float inv = 1.f / fmaxf(g_cnt[n], 1.f);
        g_h1[i] += g_acc1[i] * inv;
        g_acc1[i] = 0.f;
    }
}

// ---------------- final update + o3.Linear + sorter ----------------
__global__ void final_kernel(float* __restrict__ out,
                             const float* __restrict__ lin0, const float* __restrict__ lin1) {
    int n = blockIdx.x * blockDim.x + threadIdx.x;
    if (n >= cfg::NN) return;
    float inv = 1.f / fmaxf(g_cnt[n], 1.f);
    float h0f[16];
    #pragma unroll
    for (int s = 0; s < 16; s++) h0f[s] = g_h0[n * 16 + s] + g_acc0[n * 16 + s] * inv;
    float h1f[12];
    #pragma unroll
    for (int s = 0; s < 12; s++) h1f[s] = g_h1[n * 12 + s] + g_acc1[n * 12 + s] * inv;
    float* o = out + (size_t)n * 128;
    #pragma unroll 4
    for (int cc = 0; cc < 32; cc++) {
        float f0 = 0.f;
        #pragma unroll
        for (int s = 0; s < 16; s++) f0 = fmaf(h0f[s], lin0[s * 32 + cc], f0);
        o[4 * cc] = 0.25f * f0;
        #pragma unroll
        for (int m = 0; m < 3; m++) {
            float f1 = 0.f;
            #pragma unroll
            for (int v = 0; v < 4; v++) f1 = fmaf(h1f[v * 3 + m], lin1[v * 32 + cc], f1);
            o[4 * cc + 1 + m] = 0.5f * f1;
        }
    }
}

// ---------------- launch ----------------
extern "C" void kernel_launch(void* const* d_in, const int* in_sizes, int n_in,
                              void* d_out, int out_size) {
    const float* pos          = (const float*)d_in[0];
    const float* node_feats   = (const float*)d_in[1];
    const float* edge_attr_in = (const float*)d_in[2];
    const int*   edge_index   = (const int*)d_in[3];
    const float* enc_W  = (const float*)d_in[4];
    const float* enc_b  = (const float*)d_in[5];
    const float* ne_W1  = (const float*)d_in[6];
    const float* ne_b1  = (const float*)d_in[7];
    const float* ne_W2  = (const float*)d_in[8];
    const float* ne_b2  = (const float*)d_in[9];
    const float* ee_W1  = (const float*)d_in[10];
    const float* ee_b1  = (const float*)d_in[11];
    const float* ee_W2  = (const float*)d_in[12];
    const float* ee_b2  = (const float*)d_in[13];
    const float* re_W1  = (const float*)d_in[14];
    const float* re_b1  = (const float*)d_in[15];
    const float* re_W2  = (const float*)d_in[16];
    const float* re_b2  = (const float*)d_in[17];
    const float* fc1_W  = (const float*)d_in[18];   // [2,48,64]
    const float* fc1_b  = (const float*)d_in[19];   // [2,64]
    const float* fc2_W  = (const float*)d_in[20];   // [2,64,416]
    const float* fc2_b  = (const float*)d_in[21];   // [2,416]
    const float* lin0_W = (const float*)d_in[22];
    const float* lin1_W = (const float*)d_in[23];
    float* out = (float*)d_out;

    int dev = 0;
    cudaGetDevice(&dev);
    int nsm = 148;
    cudaDeviceGetAttribute(&nsm, cudaDevAttrMultiProcessorCount, dev);
    cudaFuncSetAttribute(conv_kernel, cudaFuncAttributeMaxDynamicSharedMemorySize, cfg::SMEM_BYTES);

    zero_kernel<<<256, 256>>>();
    node_init_kernel<<<(cfg::NN + 127) / 128, 128>>>(node_feats, enc_W, enc_b,
                                                     ne_W1, ne_b1, ne_W2, ne_b2);
    edge_init_kernel<<<(cfg::NE + 127) / 128, 128>>>(pos, edge_attr_in, edge_index,
                                                     ee_W1, ee_b1, ee_W2, ee_b2,
                                                     re_W1, re_b1, re_W2, re_b2);
    // layer 0
    conv_kernel<<<nsm, cfg::THREADS, cfg::SMEM_BYTES>>>(edge_index,
        fc1_W, fc1_b, fc2_W, fc2_b);
    update_kernel<<<(cfg::NN * 16 + 255) / 256, 256>>>();
    // layer 1
    conv_kernel<<<nsm, cfg::THREADS, cfg::SMEM_BYTES>>>(edge_index,
        fc1_W + 48 * 64, fc1_b + 64, fc2_W + 64 * 416, fc2_b + 416);
    // final
    final_kernel<<<(cfg::NN + 127) / 128, 128>>>(out, lin0_W, lin1_W);
}